// round 3
// baseline (speedup 1.0000x reference)
#include <cuda_runtime.h>
#include <cstdint>

#define TOKENS   16384
#define KDIM     4096
#define NOUT     24
#define KC       512            // K-chunk held in smem
#define NCHUNK   (KDIM / KC)    // 8
#define MT       2              // tokens per warp
#define TPC      16             // tokens per CTA (8 warps * MT)
#define THREADS  256

// Fused weight buffer: Wf[n][k] = g[k] * W_row_n[k]; rows 0-3 = W_pre, 4-7 = W_post, 8-23 = W_res
__device__ __align__(16) float g_Wf[NOUT * KDIM];

__global__ void prep_kernel(const float* __restrict__ g,
                            const float* __restrict__ Wpre,
                            const float* __restrict__ Wpost,
                            const float* __restrict__ Wres) {
    int idx = blockIdx.x * blockDim.x + threadIdx.x;
    if (idx >= NOUT * KDIM) return;
    int n = idx >> 12;            // / 4096
    int k = idx & (KDIM - 1);
    float w;
    if (n < 4)       w = Wpre[n * KDIM + k];
    else if (n < 8)  w = Wpost[(n - 4) * KDIM + k];
    else             w = Wres[(n - 8) * KDIM + k];
    g_Wf[idx] = g[k] * w;
}

__device__ __forceinline__ void cp_async16(uint32_t smem_dst, const void* gmem_src) {
    asm volatile("cp.async.cg.shared.global [%0], [%1], 16;\n" :: "r"(smem_dst), "l"(gmem_src));
}

// Load one [NOUT][KC] weight tile into smem via cp.async (3072 float4, 12 per thread)
__device__ __forceinline__ void load_tile(float* dst, int chunk, int tid) {
    uint32_t dsta = (uint32_t)__cvta_generic_to_shared(dst);
    #pragma unroll
    for (int r = 0; r < 12; r++) {
        int fid = tid + r * THREADS;      // float4 index in tile [0, 3072)
        int n   = fid >> 7;               // / (KC/4=128)
        int c4  = fid & 127;
        const float4* src = reinterpret_cast<const float4*>(g_Wf + n * KDIM + chunk * KC) + c4;
        cp_async16(dsta + (uint32_t)(fid * 16), src);
    }
    asm volatile("cp.async.commit_group;\n");
}

// Packed dual FFMA: d.lo += a.lo*b.lo; d.hi += a.hi*b.hi  (PTX-only; ptxas never emits)
__device__ __forceinline__ void ffma2(unsigned long long& d,
                                      unsigned long long a,
                                      unsigned long long b) {
    asm("fma.rn.f32x2 %0, %1, %2, %0;" : "+l"(d) : "l"(a), "l"(b));
}

__device__ __forceinline__ float unpack_sum(unsigned long long v) {
    float lo = __uint_as_float((unsigned int)(v & 0xffffffffu));
    float hi = __uint_as_float((unsigned int)(v >> 32));
    return lo + hi;
}

__device__ __forceinline__ float sigmoidf_fast(float h) {
    return 1.0f / (1.0f + __expf(-h));
}

extern __shared__ float smem[];   // 2 * NOUT * KC floats = 96 KB

__global__ void __launch_bounds__(THREADS, 1)
mhc_kernel(const float* __restrict__ X,
           const float* __restrict__ b_pre,
           const float* __restrict__ b_post,
           const float* __restrict__ b_res,
           const float* __restrict__ a_pre,
           const float* __restrict__ a_post,
           const float* __restrict__ a_res,
           float* __restrict__ out) {
    const int tid  = threadIdx.x;
    const int lane = tid & 31;
    const int warp = tid >> 5;
    const int tok0 = blockIdx.x * TPC + warp * MT;

    unsigned long long acc2[MT][NOUT];
    unsigned long long ss2[MT];
    #pragma unroll
    for (int m = 0; m < MT; m++) {
        ss2[m] = 0ull;
        #pragma unroll
        for (int n = 0; n < NOUT; n++) acc2[m][n] = 0ull;
    }

    const ulonglong2* X2 = reinterpret_cast<const ulonglong2*>(X);

    float* buf0 = smem;
    float* buf1 = smem + NOUT * KC;

    load_tile(buf0, 0, tid);
    asm volatile("cp.async.wait_group 0;\n");
    __syncthreads();

    for (int c = 0; c < NCHUNK; c++) {
        float* cur = (c & 1) ? buf1 : buf0;
        float* nxt = (c & 1) ? buf0 : buf1;
        if (c + 1 < NCHUNK) load_tile(nxt, c + 1, tid);

        // each ulonglong2 = one float4 = two packed f32x2 pairs
        const ulonglong2* xbase = X2 + (size_t)tok0 * (KDIM / 4) + c * (KC / 4);
        #pragma unroll
        for (int i = 0; i < 4; i++) {
            int p = i * 32 + lane;          // float4 index within chunk [0,128)
            ulonglong2 xv[MT];
            #pragma unroll
            for (int m = 0; m < MT; m++)
                xv[m] = xbase[(size_t)m * (KDIM / 4) + p];

            #pragma unroll
            for (int n = 0; n < NOUT; n++) {
                ulonglong2 wv = reinterpret_cast<const ulonglong2*>(cur + n * KC)[p];
                #pragma unroll
                for (int m = 0; m < MT; m++) {
                    ffma2(acc2[m][n], xv[m].x, wv.x);
                    ffma2(acc2[m][n], xv[m].y, wv.y);
                }
            }
            #pragma unroll
            for (int m = 0; m < MT; m++) {
                ffma2(ss2[m], xv[m].x, xv[m].x);
                ffma2(ss2[m], xv[m].y, xv[m].y);
            }
        }

        if (c + 1 < NCHUNK)
            asm volatile("cp.async.wait_group 0;\n");
        __syncthreads();
    }

    // Unpack packed partials, then butterfly allreduce across the 32 lanes
    float acc[MT][NOUT];
    float ss[MT];
    #pragma unroll
    for (int m = 0; m < MT; m++) {
        ss[m] = unpack_sum(ss2[m]);
        #pragma unroll
        for (int n = 0; n < NOUT; n++) acc[m][n] = unpack_sum(acc2[m][n]);
    }

    #pragma unroll
    for (int off = 16; off > 0; off >>= 1) {
        #pragma unroll
        for (int m = 0; m < MT; m++) {
            ss[m] += __shfl_xor_sync(0xffffffffu, ss[m], off);
            #pragma unroll
            for (int n = 0; n < NOUT; n++)
                acc[m][n] += __shfl_xor_sync(0xffffffffu, acc[m][n], off);
        }
    }

    // Lanes 0..MT-1 each take one token's full sums (compile-time selects, no local-mem)
    float dsel[NOUT];
    float sssel = 0.0f;
    #pragma unroll
    for (int m = 0; m < MT; m++) {
        if (lane == m) {
            sssel = ss[m];
            #pragma unroll
            for (int n = 0; n < NOUT; n++) dsel[n] = acc[m][n];
        }
    }

    if (lane < MT) {
        const int t = tok0 + lane;
        const float rinv  = rsqrtf(sssel * (1.0f / (float)KDIM) + 1e-6f);
        const float apre  = a_pre[0]  * rinv;
        const float apost = a_post[0] * rinv;
        const float ares  = a_res[0]  * rinv;

        // H_pre — one STG.128
        {
            float4 v;
            v.x = sigmoidf_fast(apre * dsel[0] + b_pre[0]);
            v.y = sigmoidf_fast(apre * dsel[1] + b_pre[1]);
            v.z = sigmoidf_fast(apre * dsel[2] + b_pre[2]);
            v.w = sigmoidf_fast(apre * dsel[3] + b_pre[3]);
            reinterpret_cast<float4*>(out)[t] = v;
        }
        // H_post — one STG.128
        {
            float4 v;
            v.x = 2.0f * sigmoidf_fast(apost * dsel[4] + b_post[0]);
            v.y = 2.0f * sigmoidf_fast(apost * dsel[5] + b_post[1]);
            v.z = 2.0f * sigmoidf_fast(apost * dsel[6] + b_post[2]);
            v.w = 2.0f * sigmoidf_fast(apost * dsel[7] + b_post[3]);
            reinterpret_cast<float4*>(out + 65536)[t] = v;
        }
        // H_res: Sinkhorn(4x4, 20 iters)
        float P[16];
        #pragma unroll
        for (int e = 0; e < 16; e++) {
            float h = ares * dsel[8 + e] + b_res[e];
            h = fminf(fmaxf(h, -15.0f), 15.0f);
            P[e] = __expf(h);
        }
        #pragma unroll 2
        for (int it = 0; it < 20; it++) {
            // column normalize (sum over rows i)
            #pragma unroll
            for (int j = 0; j < 4; j++) {
                float cs = P[j] + P[4 + j] + P[8 + j] + P[12 + j] + 1e-6f;
                float inv = __fdividef(1.0f, cs);
                P[j] *= inv; P[4 + j] *= inv; P[8 + j] *= inv; P[12 + j] *= inv;
            }
            // row normalize
            #pragma unroll
            for (int i = 0; i < 4; i++) {
                float rs = P[4 * i] + P[4 * i + 1] + P[4 * i + 2] + P[4 * i + 3] + 1e-6f;
                float inv = __fdividef(1.0f, rs);
                P[4 * i] *= inv; P[4 * i + 1] *= inv; P[4 * i + 2] *= inv; P[4 * i + 3] *= inv;
            }
        }
        // H_res — four STG.128
        float4* ores = reinterpret_cast<float4*>(out + 131072) + (size_t)t * 4;
        #pragma unroll
        for (int q = 0; q < 4; q++) {
            float4 v;
            v.x = P[4 * q]; v.y = P[4 * q + 1]; v.z = P[4 * q + 2]; v.w = P[4 * q + 3];
            ores[q] = v;
        }
    }
}

extern "C" void kernel_launch(void* const* d_in, const int* in_sizes, int n_in,
                              void* d_out, int out_size) {
    const float* X     = (const float*)d_in[0];
    const float* g     = (const float*)d_in[1];
    const float* Wpre  = (const float*)d_in[2];
    const float* Wpost = (const float*)d_in[3];
    const float* Wres  = (const float*)d_in[4];
    const float* bpre  = (const float*)d_in[5];
    const float* bpost = (const float*)d_in[6];
    const float* bres  = (const float*)d_in[7];
    const float* apre  = (const float*)d_in[8];
    const float* apost = (const float*)d_in[9];
    const float* ares  = (const float*)d_in[10];
    float* out = (float*)d_out;

    prep_kernel<<<(NOUT * KDIM + THREADS - 1) / THREADS, THREADS>>>(g, Wpre, Wpost, Wres);

    const int smem_bytes = 2 * NOUT * KC * sizeof(float);   // 98304
    cudaFuncSetAttribute(mhc_kernel, cudaFuncAttributeMaxDynamicSharedMemorySize, smem_bytes);
    mhc_kernel<<<TOKENS / TPC, THREADS, smem_bytes>>>(X, bpre, bpost, bres,
                                                      apre, apost, ares, out);
}